// round 16
// baseline (speedup 1.0000x reference)
#include <cuda_runtime.h>
#include <cuda_fp16.h>
#include <cstdint>

// ---------------------------------------------------------------------------
// Problem:
//   Ec : (128 chan, 256 s, 3 l, 128 d) f32
//   W1 : (6,128,128,1,128)  W2 : (5,128,128,2,128)  W3 : (5,128,128,3,128)
//   b1 : (6,128) b2 : (5,128) b3 : (5,128)
//   out: (128 o, 256 s, 1, 16 k) f32
// 33 conv maps: z<18 -> h=1 (kl=z/3, p=z%3); z<28 -> h=2; else h=3.
// GEMM per map: out[o,s] = sum_{a,c,d} Ec[a,s,p+c,d] * W[kl,o,a,c,d]
//   M=256(s), N=128(o), K=128*h*128 (total 13568 k64-stages across 33 maps).
// R15 = R13 +
//   (1) 444 CTAs = exactly 3 waves of 148 (h1: 8x32-stage chunks, h2: 17
//       chunks of 31/30, h3: 26 chunks of 30/29) -> per-SM makespan 91.7
//       stage-units instead of 96.
//   (2) fp16 split-K partials (halves reduce-read traffic; adds ~2.4e-4 rel).
// Warps 0-7: MMA (cp.async fp16 A from g_ecH, ldmatrix, mma.sync f32-acc).
// Warps 8-9: B producers (LDG.128 f32 W -> cvt fp16 -> STS), W read once.
// ---------------------------------------------------------------------------

#define NMAPS 33
#define SLOT_STRIDE 26            // max chunks per map (h=3: 26)
__device__ __half g_ecH[12582912];                      // Ec fp16 (25 MB)
__device__ __half g_part[NMAPS * SLOT_STRIDE * 32768];  // fp16 partials (56MB)

#define PITCH 144                 // smem row pitch: 128B fp16 data + 16B pad
#define OFF_A 0                   // A: 256 rows (s)
#define OFF_B (256 * PITCH)       // B: 128 rows (o)
#define STAGE_BYTES (384 * PITCH) // 55296
#define NSTAGE 3
#define SMEM_BYTES (NSTAGE * STAGE_BYTES)      // 165888
#define NTHREADS 320              // 8 consumer warps + 2 producer warps

// ---------------------------------------------------------------------------
__device__ __forceinline__ uint32_t smem_u32(const void* p) {
    uint32_t r;
    asm("{ .reg .u64 t; cvta.to.shared.u64 t, %1; cvt.u32.u64 %0, t; }"
        : "=r"(r) : "l"(p));
    return r;
}

__device__ __forceinline__ void ldm4(uint32_t (&r)[4], uint32_t addr) {
    asm volatile("ldmatrix.sync.aligned.m8n8.x4.shared.b16 {%0,%1,%2,%3}, [%4];"
        : "=r"(r[0]), "=r"(r[1]), "=r"(r[2]), "=r"(r[3]) : "r"(addr));
}

__device__ __forceinline__ void mma_fp16(float (&d)[4], const uint32_t (&a)[4],
                                         uint32_t b0, uint32_t b1) {
    asm volatile(
        "mma.sync.aligned.m16n8k16.row.col.f32.f16.f16.f32 "
        "{%0,%1,%2,%3}, {%4,%5,%6,%7}, {%8,%9}, {%0,%1,%2,%3};"
        : "+f"(d[0]), "+f"(d[1]), "+f"(d[2]), "+f"(d[3])
        : "r"(a[0]), "r"(a[1]), "r"(a[2]), "r"(a[3]), "r"(b0), "r"(b1));
}

__device__ __forceinline__ void cpa16(uint32_t dst, const void* src) {
    asm volatile("cp.async.cg.shared.global [%0], [%1], 16;"
        :: "r"(dst), "l"(src));
}
#define CPA_COMMIT() asm volatile("cp.async.commit_group;" ::: "memory")
#define CPA_WAIT1()  asm volatile("cp.async.wait_group 1;"  ::: "memory")

// f32x4 -> fp16x4 (8 bytes)
__device__ __forceinline__ uint2 cvt4(float4 v) {
    __half2 h01 = __floats2half2_rn(v.x, v.y);
    __half2 h23 = __floats2half2_rn(v.z, v.w);
    uint2 r;
    r.x = *reinterpret_cast<uint32_t*>(&h01);
    r.y = *reinterpret_cast<uint32_t*>(&h23);
    return r;
}

// ---------------------------------------------------------------------------
// Ec f32 -> fp16: 8 floats/thread/iter, uint4 stores.
// ---------------------------------------------------------------------------
__global__ void vrtconv_cvt_ec(const float4* __restrict__ src, int n8)
{
    uint4* dst = reinterpret_cast<uint4*>(g_ecH);
    for (int i = blockIdx.x * blockDim.x + threadIdx.x; i < n8;
         i += gridDim.x * blockDim.x) {
        float4 a = src[2 * i];
        float4 b = src[2 * i + 1];
        uint2 ra = cvt4(a);
        uint2 rb = cvt4(b);
        uint4 r; r.x = ra.x; r.y = ra.y; r.z = rb.x; r.w = rb.y;
        dst[i] = r;
    }
}

// ---------------------------------------------------------------------------
// GEMM: grid(444) = 3 exact waves. One CTA = one map z, one stage range
// [start, start+cnt) of k64 stages. Full M=256(s), full N=128(o).
// Consumers (warps 0-7): warp tile 64x64, cp.async A feed, 3-buffer ring.
// Producers (warps 8-9): stage-ahead B feed (LDG.128 f32 + cvt + STS).
// ---------------------------------------------------------------------------
__global__ __launch_bounds__(NTHREADS, 1)
void vrtconv_gemm(const float* __restrict__ W1, const float* __restrict__ W2,
                  const float* __restrict__ W3)
{
    extern __shared__ char smem[];
    const int tid  = threadIdx.x;
    const int lane = tid & 31;
    const int wid  = tid >> 5;
    const bool consumer = (wid < 8);
    const uint32_t sb = smem_u32(smem);

    // job decode: j -> (z, chunk c, h, stage range [start, start+cnt))
    const int j = blockIdx.x;
    int z, c, h, start, cnt;
    if (j < 144) {                       // h=1: 18 maps x 8 chunks of 32
        h = 1; z = j >> 3; c = j & 7;
        start = c * 32; cnt = 32;
    } else if (j < 314) {                // h=2: 10 maps x 17 chunks (31/30)
        h = 2; int t = j - 144; z = 18 + t / 17; c = t % 17;
        cnt   = (c < 2) ? 31 : 30;
        start = (c < 2) ? c * 31 : 62 + (c - 2) * 30;   // 2*31+15*30=512
    } else {                             // h=3: 5 maps x 26 chunks (30/29)
        h = 3; int t = j - 314; z = 28 + t / 26; c = t % 26;
        cnt   = (c < 14) ? 30 : 29;
        start = (c < 14) ? c * 30 : 420 + (c - 14) * 29; // 14*30+12*29=768
    }

    int kl, p; const float* W;
    if (h == 1)      { kl = z / 3;         p = z % 3;        W = W1; }
    else if (h == 2) { kl = (z - 18) >> 1; p = (z - 18) & 1; W = W2; }
    else             { kl = z - 28;        p = 0;            W = W3; }

    const size_t oStride = (size_t)16384 * h;        // o-stride in W (f32)
    const float* Wk = W + (size_t)kl * 2097152 * (size_t)h;
    const __half* ecH = g_ecH;

    if (consumer) {
        // ---------------- consumer warps: MMA pipeline --------------------
        const int wm = wid & 3;      // 4 m-warps (64 s each)
        const int wn = wid >> 2;     // 2 n-warps (64 o each)

        float acc[4][8][4];
        #pragma unroll
        for (int a = 0; a < 4; ++a)
            #pragma unroll
            for (int b = 0; b < 8; ++b)
                #pragma unroll
                for (int cc = 0; cc < 4; ++cc) acc[a][b][cc] = 0.0f;

        // global stage st: pair q = st>>1, d-block d0 = (st&1)*64
        auto cpaA = [&](int st, int ring) {
            const int q = st >> 1;
            int a, cl;
            if (h == 1)      { a = q;      cl = 0;     }
            else if (h == 2) { a = q >> 1; cl = q & 1; }
            else             { a = q / 3;  cl = q % 3; }
            const int d0 = (st & 1) * 64;
            const __half* src = ecH + (size_t)a * 98304
                              + (size_t)(p + cl) * 128 + d0;
            const uint32_t sa = sb + (uint32_t)(ring * STAGE_BYTES) + OFF_A;
            #pragma unroll
            for (int i = 0; i < 8; ++i) {          // 256 rows x 8 x 16B
                const int flat = i * 256 + tid;
                const int row = flat >> 3, cc = flat & 7;
                cpa16(sa + row * PITCH + cc * 16,
                      src + (size_t)row * 384 + cc * 8);
            }
        };

        const uint32_t aByte = (uint32_t)((wm * 64 + (lane & 15)) * PITCH
                                          + (lane >> 4) * 16);
        const uint32_t bByte = (uint32_t)((wn * 64 + (lane & 15)) * PITCH
                                          + (lane >> 4) * 16);

        cpaA(start, 0);     CPA_COMMIT();
        cpaA(start + 1, 1); CPA_COMMIT();

        int ring = 0;
        for (int i = 0; i < cnt; ++i) {
            CPA_WAIT1();
            __syncthreads();                       // stage i (A & B) ready

            const uint32_t bufb = sb + (uint32_t)(ring * STAGE_BYTES);
            #pragma unroll
            for (int kk = 0; kk < 4; ++kk) {       // k64 = 4 x k16
                uint32_t af[4][4], bf[4][4];
                #pragma unroll
                for (int mt = 0; mt < 4; ++mt)
                    ldm4(af[mt], bufb + OFF_A + aByte + mt * (16 * PITCH) + kk * 32);
                #pragma unroll
                for (int nj = 0; nj < 4; ++nj)
                    ldm4(bf[nj], bufb + OFF_B + bByte + nj * (16 * PITCH) + kk * 32);
                #pragma unroll
                for (int mt = 0; mt < 4; ++mt)
                    #pragma unroll
                    for (int nj = 0; nj < 4; ++nj) {
                        mma_fp16(acc[mt][nj * 2],     af[mt], bf[nj][0], bf[nj][2]);
                        mma_fp16(acc[mt][nj * 2 + 1], af[mt], bf[nj][1], bf[nj][3]);
                    }
            }

            if (i + 2 < cnt) {
                int r2 = ring + 2; if (r2 >= 3) r2 -= 3;
                cpaA(start + i + 2, r2);
            }
            CPA_COMMIT();
            if (++ring == 3) ring = 0;
        }

        // epilogue: fp16 partials [map][chunk][o:128][s:256]
        __half* dst = g_part + ((size_t)z * SLOT_STRIDE + c) * 32768;
        #pragma unroll
        for (int mt = 0; mt < 4; ++mt) {
            const int s0 = wm * 64 + mt * 16 + (lane >> 2);
            #pragma unroll
            for (int n8 = 0; n8 < 8; ++n8) {
                const int o = wn * 64 + n8 * 8 + (lane & 3) * 2;
                dst[(size_t)o * 256 + s0]           = __float2half_rn(acc[mt][n8][0]);
                dst[(size_t)(o + 1) * 256 + s0]     = __float2half_rn(acc[mt][n8][1]);
                dst[(size_t)o * 256 + s0 + 8]       = __float2half_rn(acc[mt][n8][2]);
                dst[(size_t)(o + 1) * 256 + s0 + 8] = __float2half_rn(acc[mt][n8][3]);
            }
        }
    } else {
        // ---------------- producer warps: B feed (f32 -> fp16) ------------
        const int ptid = tid - 256;               // 0..63
        float4 bs[2][16];                          // two 16-float4 batches

        // load stage st's B (128 rows x 64 f32 = 2048 float4, 32/thread)
        auto ldgB = [&](int st) {
            const int q  = st >> 1;
            const int d0 = (st & 1) * 64;
            const float* src = Wk + (size_t)q * 128 + d0;
            #pragma unroll
            for (int hf = 0; hf < 2; ++hf)
                #pragma unroll
                for (int i = 0; i < 16; ++i) {
                    const int flat = hf * 1024 + i * 64 + ptid;
                    const int row = flat >> 4, c4 = flat & 15;
                    bs[hf][i] = *reinterpret_cast<const float4*>(
                        src + (size_t)row * oStride + c4 * 4);
                }
        };
        auto stsB = [&](int ring) {
            char* base = smem + ring * STAGE_BYTES + OFF_B;
            #pragma unroll
            for (int hf = 0; hf < 2; ++hf)
                #pragma unroll
                for (int i = 0; i < 16; ++i) {
                    const int flat = hf * 1024 + i * 64 + ptid;
                    const int row = flat >> 4, c4 = flat & 15;
                    *reinterpret_cast<uint2*>(base + row * PITCH + c4 * 8)
                        = cvt4(bs[hf][i]);
                }
        };

        // prologue: stage 0 fully staged before first barrier
        ldgB(start);
        stsB(0);

        int ring = 0;
        for (int i = 0; i < cnt; ++i) {
            __syncthreads();                       // pairs with consumer barrier
            if (i + 1 < cnt) {                     // produce stage i+1
                int r1 = ring + 1; if (r1 >= 3) r1 -= 3;
                ldgB(start + i + 1);
                stsB(r1);
            }
            if (++ring == 3) ring = 0;
        }
    }
}

// ---------------------------------------------------------------------------
// Single-pass reduce: block = (o, k). 2048 blocks x 256 threads (thread = s).
// Sums the map's chunks (8/17/26 for h=1/2/3), + bias, max over p, ReLU.
// ---------------------------------------------------------------------------
__global__ void vrtconv_reduce(const float* __restrict__ b1,
                               const float* __restrict__ b2,
                               const float* __restrict__ b3,
                               float* __restrict__ out)
{
    const int o = blockIdx.x >> 4;
    const int k = blockIdx.x & 15;
    const int s = threadIdx.x;

    const int h_idx = k % 3;       // k = h_idx + 3*jj
    const int jj    = k / 3;
    const int P     = 3 - h_idx;
    const int base  = (h_idx == 0) ? 0 : (h_idx == 1 ? 18 : 28);
    const int nch   = (h_idx == 0) ? 8 : (h_idx == 1 ? 17 : 26);
    const float* bb = (h_idx == 0) ? b1 : (h_idx == 1 ? b2 : b3);
    const float bias = bb[jj * 128 + o];

    float m = -1e30f;
    for (int pp = 0; pp < P; ++pp) {
        const int zmap = base + jj * P + pp;
        const __half* q = g_part + (size_t)zmap * SLOT_STRIDE * 32768
                        + (size_t)o * 256 + s;
        float sum = 0.0f;
        #pragma unroll 8
        for (int cc = 0; cc < nch; ++cc)
            sum += __half2float(q[(size_t)cc * 32768]);
        m = fmaxf(m, sum + bias);
    }
    out[((size_t)o * 256 + s) * 16 + k] = fmaxf(m, 0.0f);
}

// ---------------------------------------------------------------------------
extern "C" void kernel_launch(void* const* d_in, const int* in_sizes, int n_in,
                              void* d_out, int out_size) {
    const float* Ec = (const float*)d_in[0];
    const float* W1 = (const float*)d_in[1];
    const float* W2 = (const float*)d_in[2];
    const float* W3 = (const float*)d_in[3];
    const float* b1 = (const float*)d_in[4];
    const float* b2 = (const float*)d_in[5];
    const float* b3 = (const float*)d_in[6];
    float* out = (float*)d_out;

    vrtconv_cvt_ec<<<1536, 256>>>((const float4*)Ec, 12582912 / 8);

    cudaFuncSetAttribute(vrtconv_gemm,
                         cudaFuncAttributeMaxDynamicSharedMemorySize, SMEM_BYTES);
    vrtconv_gemm<<<444, NTHREADS, SMEM_BYTES>>>(W1, W2, W3);

    vrtconv_reduce<<<2048, 256>>>(b1, b2, b3, out);
}

// round 17
// speedup vs baseline: 1.1714x; 1.1714x over previous
#include <cuda_runtime.h>
#include <cuda_fp16.h>
#include <cstdint>

// ---------------------------------------------------------------------------
// Problem:
//   Ec : (128 chan, 256 s, 3 l, 128 d) f32
//   W1 : (6,128,128,1,128)  W2 : (5,128,128,2,128)  W3 : (5,128,128,3,128)
//   b1 : (6,128) b2 : (5,128) b3 : (5,128)
//   out: (128 o, 256 s, 1, 16 k) f32
// 33 conv maps: z<18 -> h=1 (kl=z/3, p=z%3); z<28 -> h=2; else h=3.
// GEMM per map: out[o,s] = sum_{a,c,d} Ec[a,s,p+c,d] * W[kl,o,a,c,d]
//   M=256(s), N=128(o), K=128*h*128.
// R16 = R13 (best GEMM config: 424 uniform CTAs, 32 compile-time k64 stages,
// 3-buffer ring, warp-specialized B feed) + fp16 split-K partials (proven in
// R15: rel_err 3.3e-4, halves epilogue-write + reduce-read traffic).
// Warps 0-7: MMA (cp.async fp16 A from g_ecH, ldmatrix, mma.sync f32-acc).
// Warps 8-9: B producers (LDG.128 f32 W -> cvt fp16 -> STS), W read once.
// ---------------------------------------------------------------------------

#define NMAPS 33
#define SLOT_STRIDE 24            // max chunks per map = 8*h <= 24
__device__ __half g_ecH[12582912];                      // Ec fp16 (25 MB)
__device__ __half g_part[NMAPS * SLOT_STRIDE * 32768];  // fp16 partials (52MB)

#define PITCH 144                 // smem row pitch: 128B fp16 data + 16B pad
#define OFF_A 0                   // A: 256 rows (s)
#define OFF_B (256 * PITCH)       // B: 128 rows (o)
#define STAGE_BYTES (384 * PITCH) // 55296
#define NSTAGE 3
#define SMEM_BYTES (NSTAGE * STAGE_BYTES)      // 165888
#define NTHREADS 320              // 8 consumer warps + 2 producer warps
#define NST 32                    // k64 stages per K=2048 chunk

// ---------------------------------------------------------------------------
__device__ __forceinline__ uint32_t smem_u32(const void* p) {
    uint32_t r;
    asm("{ .reg .u64 t; cvta.to.shared.u64 t, %1; cvt.u32.u64 %0, t; }"
        : "=r"(r) : "l"(p));
    return r;
}

__device__ __forceinline__ void ldm4(uint32_t (&r)[4], uint32_t addr) {
    asm volatile("ldmatrix.sync.aligned.m8n8.x4.shared.b16 {%0,%1,%2,%3}, [%4];"
        : "=r"(r[0]), "=r"(r[1]), "=r"(r[2]), "=r"(r[3]) : "r"(addr));
}

__device__ __forceinline__ void mma_fp16(float (&d)[4], const uint32_t (&a)[4],
                                         uint32_t b0, uint32_t b1) {
    asm volatile(
        "mma.sync.aligned.m16n8k16.row.col.f32.f16.f16.f32 "
        "{%0,%1,%2,%3}, {%4,%5,%6,%7}, {%8,%9}, {%0,%1,%2,%3};"
        : "+f"(d[0]), "+f"(d[1]), "+f"(d[2]), "+f"(d[3])
        : "r"(a[0]), "r"(a[1]), "r"(a[2]), "r"(a[3]), "r"(b0), "r"(b1));
}

__device__ __forceinline__ void cpa16(uint32_t dst, const void* src) {
    asm volatile("cp.async.cg.shared.global [%0], [%1], 16;"
        :: "r"(dst), "l"(src));
}
#define CPA_COMMIT() asm volatile("cp.async.commit_group;" ::: "memory")
#define CPA_WAIT1()  asm volatile("cp.async.wait_group 1;"  ::: "memory")

// f32x4 -> fp16x4 (8 bytes)
__device__ __forceinline__ uint2 cvt4(float4 v) {
    __half2 h01 = __floats2half2_rn(v.x, v.y);
    __half2 h23 = __floats2half2_rn(v.z, v.w);
    uint2 r;
    r.x = *reinterpret_cast<uint32_t*>(&h01);
    r.y = *reinterpret_cast<uint32_t*>(&h23);
    return r;
}

// ---------------------------------------------------------------------------
// Ec f32 -> fp16: 8 floats/thread/iter, uint4 stores.
// ---------------------------------------------------------------------------
__global__ void vrtconv_cvt_ec(const float4* __restrict__ src, int n8)
{
    uint4* dst = reinterpret_cast<uint4*>(g_ecH);
    for (int i = blockIdx.x * blockDim.x + threadIdx.x; i < n8;
         i += gridDim.x * blockDim.x) {
        float4 a = src[2 * i];
        float4 b = src[2 * i + 1];
        uint2 ra = cvt4(a);
        uint2 rb = cvt4(b);
        uint4 r; r.x = ra.x; r.y = ra.y; r.z = rb.x; r.w = rb.y;
        dst[i] = r;
    }
}

// ---------------------------------------------------------------------------
// GEMM: grid(424). One CTA = one map z, one K-chunk of 16 (a,c) pairs
// (K=2048), full M=256(s), full N=128(o). 32 stages of k64, 3-buffer ring.
// Consumers (warps 0-7): warp tile 64x64, cp.async A feed.
// Producers (warps 8-9): stage-ahead B feed (LDG.128 f32 + cvt + STS).
// ---------------------------------------------------------------------------
__global__ __launch_bounds__(NTHREADS, 1)
void vrtconv_gemm(const float* __restrict__ W1, const float* __restrict__ W2,
                  const float* __restrict__ W3)
{
    extern __shared__ char smem[];
    const int tid  = threadIdx.x;
    const int lane = tid & 31;
    const int wid  = tid >> 5;
    const bool consumer = (wid < 8);
    const uint32_t sb = smem_u32(smem);

    // job decode: j -> (z, chunk, h)
    const int j = blockIdx.x;
    int z, chunk, h;
    if (j < 144)      { z = j >> 3;                  chunk = j & 7;    h = 1; }
    else if (j < 304) { int t = j - 144; z = 18 + (t >> 4); chunk = t & 15; h = 2; }
    else              { int t = j - 304; z = 28 + t / 24;   chunk = t % 24; h = 3; }

    int kl, p; const float* W;
    if (h == 1)      { kl = z / 3;         p = z % 3;        W = W1; }
    else if (h == 2) { kl = (z - 18) >> 1; p = (z - 18) & 1; W = W2; }
    else             { kl = z - 28;        p = 0;            W = W3; }

    const size_t oStride = (size_t)16384 * h;        // o-stride in W (f32)
    const float* Wk = W + (size_t)kl * 2097152 * (size_t)h;
    const __half* ecH = g_ecH;

    if (consumer) {
        // ---------------- consumer warps: MMA pipeline --------------------
        const int wm = wid & 3;      // 4 m-warps (64 s each)
        const int wn = wid >> 2;     // 2 n-warps (64 o each)

        float acc[4][8][4];
        #pragma unroll
        for (int a = 0; a < 4; ++a)
            #pragma unroll
            for (int b = 0; b < 8; ++b)
                #pragma unroll
                for (int c = 0; c < 4; ++c) acc[a][b][c] = 0.0f;

        // stage st: pair q = chunk*16 + (st>>1), d-block d0 = (st&1)*64
        auto cpaA = [&](int st) {
            const int q = chunk * 16 + (st >> 1);
            int a, cl;
            if (h == 1)      { a = q;      cl = 0;     }
            else if (h == 2) { a = q >> 1; cl = q & 1; }
            else             { a = q / 3;  cl = q % 3; }
            const int d0 = (st & 1) * 64;
            const __half* src = ecH + (size_t)a * 98304
                              + (size_t)(p + cl) * 128 + d0;
            const uint32_t sa = sb + (uint32_t)((st % 3) * STAGE_BYTES) + OFF_A;
            #pragma unroll
            for (int i = 0; i < 8; ++i) {          // 256 rows x 8 x 16B
                const int flat = i * 256 + tid;
                const int row = flat >> 3, c = flat & 7;
                cpa16(sa + row * PITCH + c * 16,
                      src + (size_t)row * 384 + c * 8);
            }
        };

        const uint32_t aByte = (uint32_t)((wm * 64 + (lane & 15)) * PITCH
                                          + (lane >> 4) * 16);
        const uint32_t bByte = (uint32_t)((wn * 64 + (lane & 15)) * PITCH
                                          + (lane >> 4) * 16);

        cpaA(0); CPA_COMMIT();
        cpaA(1); CPA_COMMIT();

        for (int st = 0; st < NST; ++st) {
            CPA_WAIT1();
            __syncthreads();                       // stage st (A & B) ready

            const uint32_t bufb = sb + (uint32_t)((st % 3) * STAGE_BYTES);
            #pragma unroll
            for (int kk = 0; kk < 4; ++kk) {       // k64 = 4 x k16
                uint32_t af[4][4], bf[4][4];
                #pragma unroll
                for (int mt = 0; mt < 4; ++mt)
                    ldm4(af[mt], bufb + OFF_A + aByte + mt * (16 * PITCH) + kk * 32);
                #pragma unroll
                for (int nj = 0; nj < 4; ++nj)
                    ldm4(bf[nj], bufb + OFF_B + bByte + nj * (16 * PITCH) + kk * 32);
                #pragma unroll
                for (int mt = 0; mt < 4; ++mt)
                    #pragma unroll
                    for (int nj = 0; nj < 4; ++nj) {
                        mma_fp16(acc[mt][nj * 2],     af[mt], bf[nj][0], bf[nj][2]);
                        mma_fp16(acc[mt][nj * 2 + 1], af[mt], bf[nj][1], bf[nj][3]);
                    }
            }

            if (st + 2 < NST) cpaA(st + 2);
            CPA_COMMIT();
        }

        // epilogue: fp16 partials [map][chunk][o:128][s:256]
        __half* dst = g_part + ((size_t)z * SLOT_STRIDE + chunk) * 32768;
        #pragma unroll
        for (int mt = 0; mt < 4; ++mt) {
            const int s0 = wm * 64 + mt * 16 + (lane >> 2);
            #pragma unroll
            for (int n8 = 0; n8 < 8; ++n8) {
                const int o = wn * 64 + n8 * 8 + (lane & 3) * 2;
                dst[(size_t)o * 256 + s0]           = __float2half_rn(acc[mt][n8][0]);
                dst[(size_t)(o + 1) * 256 + s0]     = __float2half_rn(acc[mt][n8][1]);
                dst[(size_t)o * 256 + s0 + 8]       = __float2half_rn(acc[mt][n8][2]);
                dst[(size_t)(o + 1) * 256 + s0 + 8] = __float2half_rn(acc[mt][n8][3]);
            }
        }
    } else {
        // ---------------- producer warps: B feed (f32 -> fp16) ------------
        const int ptid = tid - 256;               // 0..63
        float4 bs[2][16];                          // two 16-float4 batches

        // load stage st's B (128 rows x 64 f32 = 2048 float4, 32/thread)
        auto ldgB = [&](int st) {
            const int q  = chunk * 16 + (st >> 1);
            const int d0 = (st & 1) * 64;
            const float* src = Wk + (size_t)q * 128 + d0;
            #pragma unroll
            for (int hf = 0; hf < 2; ++hf)
                #pragma unroll
                for (int i = 0; i < 16; ++i) {
                    const int flat = hf * 1024 + i * 64 + ptid;
                    const int row = flat >> 4, c4 = flat & 15;
                    bs[hf][i] = *reinterpret_cast<const float4*>(
                        src + (size_t)row * oStride + c4 * 4);
                }
        };
        auto stsB = [&](int st) {
            char* base = smem + (st % 3) * STAGE_BYTES + OFF_B;
            #pragma unroll
            for (int hf = 0; hf < 2; ++hf)
                #pragma unroll
                for (int i = 0; i < 16; ++i) {
                    const int flat = hf * 1024 + i * 64 + ptid;
                    const int row = flat >> 4, c4 = flat & 15;
                    *reinterpret_cast<uint2*>(base + row * PITCH + c4 * 8)
                        = cvt4(bs[hf][i]);
                }
        };

        // prologue: stage 0 fully staged before first barrier
        ldgB(0);
        stsB(0);

        for (int st = 0; st < NST; ++st) {
            __syncthreads();                       // pairs with consumer barrier
            if (st + 1 < NST) {                    // produce stage st+1
                ldgB(st + 1);
                stsB(st + 1);
            }
        }
    }
}

// ---------------------------------------------------------------------------
// Single-pass reduce: block = (o, k). 2048 blocks x 256 threads (thread = s).
// Each thread: sum 8h fp16 chunks for each of P maps, + bias, max, ReLU.
// ---------------------------------------------------------------------------
__global__ void vrtconv_reduce(const float* __restrict__ b1,
                               const float* __restrict__ b2,
                               const float* __restrict__ b3,
                               float* __restrict__ out)
{
    const int o = blockIdx.x >> 4;
    const int k = blockIdx.x & 15;
    const int s = threadIdx.x;

    const int h_idx = k % 3;       // k = h_idx + 3*jj
    const int jj    = k / 3;
    const int P     = 3 - h_idx;
    const int base  = (h_idx == 0) ? 0 : (h_idx == 1 ? 18 : 28);
    const int nch   = 8 * (h_idx + 1);
    const float* bb = (h_idx == 0) ? b1 : (h_idx == 1 ? b2 : b3);
    const float bias = bb[jj * 128 + o];

    float m = -1e30f;
    for (int pp = 0; pp < P; ++pp) {
        const int zmap = base + jj * P + pp;
        const __half* q = g_part + (size_t)zmap * SLOT_STRIDE * 32768
                        + (size_t)o * 256 + s;
        float sum = 0.0f;
        #pragma unroll 8
        for (int cc = 0; cc < nch; ++cc)
            sum += __half2float(q[(size_t)cc * 32768]);
        m = fmaxf(m, sum + bias);
    }
    out[((size_t)o * 256 + s) * 16 + k] = fmaxf(m, 0.0f);
}

// ---------------------------------------------------------------------------
extern "C" void kernel_launch(void* const* d_in, const int* in_sizes, int n_in,
                              void* d_out, int out_size) {
    const float* Ec = (const float*)d_in[0];
    const float* W1 = (const float*)d_in[1];
    const float* W2 = (const float*)d_in[2];
    const float* W3 = (const float*)d_in[3];
    const float* b1 = (const float*)d_in[4];
    const float* b2 = (const float*)d_in[5];
    const float* b3 = (const float*)d_in[6];
    float* out = (float*)d_out;

    vrtconv_cvt_ec<<<1536, 256>>>((const float4*)Ec, 12582912 / 8);

    cudaFuncSetAttribute(vrtconv_gemm,
                         cudaFuncAttributeMaxDynamicSharedMemorySize, SMEM_BYTES);
    vrtconv_gemm<<<424, NTHREADS, SMEM_BYTES>>>(W1, W2, W3);

    vrtconv_reduce<<<2048, 256>>>(b1, b2, b3, out);
}